// round 10
// baseline (speedup 1.0000x reference)
#include <cuda_runtime.h>
#include <cuda_fp16.h>

// Problem constants
#define Bn 8
#define Hn 64
#define Wn 2048
#define HWn (Hn * Wn)          // 131072
#define CHWn (4 * HWn)         // 524288

// Fused-kernel tile: 128x16 output, +-6 x / +-3 y halo for 3 iterations
#define TX 128
#define TY 16
#define EX 140
#define EY 22
#define NEXT (EX * EY)         // 3080
#define NTHREADS 512

// Setup-kernel tile
#define STY 8
#define SNT 256
#define SHX (TX + 4)           // 132
#define SHY (STY + 2)          // 10
#define SHALO (SHX * SHY)      // 1320

// Separable Gaussian weights: exp(-d^2/(2*0.9^2)) for d=1,2
#define W1f 0.53940751f
#define W4f 0.08465798f

// C2 = -1/(2*0.015^2) * log2(e)
#define C2f      (-3206.0005353f)
#define NEG2C2f  (6412.0010706f)
#define L2Ef     (1.4426950408889634f)
#define MASK_BIG (1.0e9f)
#define SKIP_THR (-40.0f)

#define SMEM_BYTES (3 * NEXT * (int)sizeof(uint2))   // 73920

// Iteration-invariant appearance data (allocation forbidden -> device globals)
__device__ unsigned char g_alive[Bn * HWn];
__device__ float         g_beta[Bn * HWn * 14];

// ---- helpers ----
__device__ __forceinline__ float ex2(float x) {
    float r;
    asm("ex2.approx.ftz.f32 %0, %1;" : "=f"(r) : "f"(x));
    return r;
}
__device__ __forceinline__ __half2 u2h(unsigned u) {
    __half2 h;
    *reinterpret_cast<unsigned*>(&h) = u;
    return h;
}
__device__ __forceinline__ unsigned h2u(__half2 h) {
    return *reinterpret_cast<unsigned*>(&h);
}
__device__ __forceinline__ float4 softmax4(float4 q) {
    const float mx = fmaxf(fmaxf(q.x, q.y), fmaxf(q.z, q.w));
    const float p0 = ex2((q.x - mx) * L2Ef);
    const float p1 = ex2((q.y - mx) * L2Ef);
    const float p2 = ex2((q.z - mx) * L2Ef);
    const float p3 = ex2((q.w - mx) * L2Ef);
    const float inv = __fdividef(1.0f, p0 + p1 + p2 + p3);
    return make_float4(p0 * inv, p1 * inv, p2 * inv, p3 * inv);
}

// ============================================================================
// Setup: per-pixel alive flag + (rare) exact beta taps. Iteration-invariant.
// ============================================================================
__global__ __launch_bounds__(SNT)
void crf_setup(const float* __restrict__ xyz,
               const float* __restrict__ mask)
{
    __shared__ float4 sG[SHALO];

    const int b   = blockIdx.z;
    const int ty0 = blockIdx.y * STY;
    const int tx0 = blockIdx.x * TX;
    const int tid = threadIdx.x;

    const float* __restrict__ Xb = xyz  + b * 3 * HWn;
    const float* __restrict__ Mb = mask + b * HWn;

    for (int i = tid; i < SHALO; i += SNT) {
        const int hy = i / SHX;
        const int hx = i - hy * SHX;
        const int gy = ty0 + hy - 1;
        const int gx = tx0 + hx - 2;
        float4 sg = make_float4(0.f, 0.f, 0.f, -MASK_BIG);
        if (gy >= 0 && gy < Hn && gx >= 0 && gx < Wn) {
            const int g = gy * Wn + gx;
            const float x = Xb[g];
            const float y = Xb[g + HWn];
            const float z = Xb[g + 2 * HWn];
            const float m = Mb[g];
            float nrm = x * x;
            nrm = fmaf(y, y, nrm);
            nrm = fmaf(z, z, nrm);
            sg.x = x; sg.y = y; sg.z = z;
            sg.w = fmaf(nrm, C2f, fmaf(m, MASK_BIG, -MASK_BIG));
        }
        sG[i] = sg;
    }
    __syncthreads();

    const int offs[14] = {
        -SHX - 2, -SHX - 1, -SHX, -SHX + 1, -SHX + 2,
               -2,       -1,            1,        2,
         SHX - 2,  SHX - 1,  SHX,  SHX + 1,  SHX + 2
    };

    for (int k = 0; k < (TX * STY) / SNT; ++k) {
        const int p  = tid + k * SNT;
        const int ty = p >> 7;
        const int tx = p & (TX - 1);
        const int base = (ty + 1) * SHX + (tx + 2);

        const float4 ga = sG[base];
        const float axs = ga.x * NEG2C2f;
        const float ays = ga.y * NEG2C2f;
        const float azs = ga.z * NEG2C2f;
        const float na  = ga.w;

        float maxa = -MASK_BIG;
        #pragma unroll
        for (int t = 0; t < 14; ++t) {
            const float4 gn = sG[base + offs[t]];
            const float arg = fmaf(gn.x, axs,
                              fmaf(gn.y, ays,
                              fmaf(gn.z, azs, gn.w + na)));
            maxa = fmaxf(maxa, arg);
        }

        const bool alive = (maxa > SKIP_THR) && (na > -1.0e8f);
        const int pix = b * HWn + (ty0 + ty) * Wn + (tx0 + tx);
        g_alive[pix] = alive ? 1 : 0;

        if (alive) {
            #pragma unroll
            for (int t = 0; t < 14; ++t) {
                const float4 gn = sG[base + offs[t]];
                const float arg = fmaf(gn.x, axs,
                                  fmaf(gn.y, ays,
                                  fmaf(gn.z, azs, gn.w + na)));
                g_beta[pix * 14 + t] = ex2(arg);
            }
        }
    }
}

// ============================================================================
// One in-smem CRF iteration; 2 x-adjacent points per thread via uint4.
// ============================================================================
template<int IT, bool LAST>
__device__ __forceinline__ void crf_do_iter(
    const uint2* __restrict__ sQin, uint2* __restrict__ sQout,
    uint2* __restrict__ sH,
    const int b, const int ty0, const int tx0, const int tid,
    const float* __restrict__ unary, float* __restrict__ out,
    const __half2 w1h, const __half2 w4h,
    const __half2 wa01, const __half2 wa23,
    const __half2 ws01, const __half2 ws23,
    const __half2 ccA0, const __half2 ccA1, const __half2 ccA2, const __half2 ccA3,
    const __half2 ccB0, const __half2 ccB1, const __half2 ccB2, const __half2 ccB3)
{
    constexpr int HR0 = IT, HR1 = EY - IT;
    constexpr int HC0 = 2 * IT + 2;
    constexpr int HWID = EX - 4 - 4 * IT;   // 136 / 132 / 128
    constexpr int PP   = HWID / 2;          // 68 / 66 / 64 pairs per row
    constexpr int EP   = PP - 64;           // 4 / 2 / 0 extra pairs
    constexpr int LOG2EP = (EP == 4) ? 2 : 1;
    constexpr int UR0 = IT + 1, UR1 = EY - 1 - IT;

    // ---- Horizontal 5-tap pass on point pairs ----
    auto h_pair = [&](int c) {   // c even: points c, c+1
        const uint4 A = *reinterpret_cast<const uint4*>(&sQin[c - 2]);
        const uint4 B = *reinterpret_cast<const uint4*>(&sQin[c]);
        const uint4 C = *reinterpret_cast<const uint4*>(&sQin[c + 2]);
        const __half2 h00 = __hfma2(w4h, __hadd2(u2h(A.x), u2h(C.x)),
                            __hfma2(w1h, __hadd2(u2h(A.z), u2h(B.z)), u2h(B.x)));
        const __half2 h01 = __hfma2(w4h, __hadd2(u2h(A.y), u2h(C.y)),
                            __hfma2(w1h, __hadd2(u2h(A.w), u2h(B.w)), u2h(B.y)));
        const __half2 h10 = __hfma2(w4h, __hadd2(u2h(A.z), u2h(C.z)),
                            __hfma2(w1h, __hadd2(u2h(B.x), u2h(C.x)), u2h(B.z)));
        const __half2 h11 = __hfma2(w4h, __hadd2(u2h(A.w), u2h(C.w)),
                            __hfma2(w1h, __hadd2(u2h(B.y), u2h(C.y)), u2h(B.w)));
        *reinterpret_cast<uint4*>(&sH[c]) =
            make_uint4(h2u(h00), h2u(h01), h2u(h10), h2u(h11));
    };

    {
        const int px = tid & 63;
        for (int r = HR0 + (tid >> 6); r < HR1; r += NTHREADS >> 6)
            h_pair(r * EX + HC0 + 2 * px);
        if (EP > 0) {
            const int px2 = 64 + (tid & (EP - 1));
            const int r = HR0 + (tid >> LOG2EP);
            if (r < HR1) h_pair(r * EX + HC0 + 2 * px2);
        }
    }
    __syncthreads();

    // ---- Vertical 3-tap + update on point pairs ----
    auto u_pair = [&](int row, int col) {   // col even: pixels col, col+1
        const int c  = row * EX + col;
        const int gy = ty0 + row - 3;
        const int gx = tx0 + col - 6;       // even; pair never straddles W edge
        if (!LAST) {
            if (gy < 0 || gy >= Hn || gx < 0 || gx >= Wn) {
                *reinterpret_cast<uint4*>(&sQout[c]) = make_uint4(0u, 0u, 0u, 0u);
                return;
            }
        }
        const int g   = gy * Wn + gx;
        const int pix = b * HWn + g;
        const int gg  = b * CHWn + g;

        const uint4 HM = *reinterpret_cast<const uint4*>(&sH[c - EX]);
        const uint4 H0 = *reinterpret_cast<const uint4*>(&sH[c]);
        const uint4 HP = *reinterpret_cast<const uint4*>(&sH[c + EX]);
        const uint4 QC = *reinterpret_cast<const uint4*>(&sQin[c]);

        // S = H0 + W1*(Hm+Hp) - Qc   for both points, both channel pairs
        const __half2 sA01 = __hsub2(
            __hfma2(w1h, __hadd2(u2h(HM.x), u2h(HP.x)), u2h(H0.x)), u2h(QC.x));
        const __half2 sA23 = __hsub2(
            __hfma2(w1h, __hadd2(u2h(HM.y), u2h(HP.y)), u2h(H0.y)), u2h(QC.y));
        const __half2 sB01 = __hsub2(
            __hfma2(w1h, __hadd2(u2h(HM.z), u2h(HP.z)), u2h(H0.z)), u2h(QC.z));
        const __half2 sB23 = __hsub2(
            __hfma2(w1h, __hadd2(u2h(HM.w), u2h(HP.w)), u2h(H0.w)), u2h(QC.w));

        // alive flags for both pixels in one 16-bit load (pix is even)
        const unsigned short al2 =
            *reinterpret_cast<const unsigned short*>(&g_alive[pix]);

        __half2 aA01 = __float2half2_rn(0.f), aA23 = aA01;
        __half2 aB01 = aA01, aB23 = aA01;
        if (al2) {
            const int offs[14] = {
                -EX - 2, -EX - 1, -EX, -EX + 1, -EX + 2,
                      -2,      -1,           1,       2,
                 EX - 2,  EX - 1,  EX,  EX + 1,  EX + 2
            };
            if (al2 & 0x00FFu) {
                const float* __restrict__ bp = g_beta + (size_t)pix * 14;
                #pragma unroll
                for (int t = 0; t < 14; ++t) {
                    const __half2 bmh = __float2half2_rn(bp[t]);
                    const uint2 q = sQin[c + offs[t]];
                    aA01 = __hfma2(bmh, u2h(q.x), aA01);
                    aA23 = __hfma2(bmh, u2h(q.y), aA23);
                }
            }
            if (al2 & 0xFF00u) {
                const float* __restrict__ bp = g_beta + (size_t)(pix + 1) * 14;
                #pragma unroll
                for (int t = 0; t < 14; ++t) {
                    const __half2 bmh = __float2half2_rn(bp[t]);
                    const uint2 q = sQin[c + 1 + offs[t]];
                    aB01 = __hfma2(bmh, u2h(q.x), aB01);
                    aB23 = __hfma2(bmh, u2h(q.y), aB23);
                }
            }
        }

        // Paired unary loads (gx even -> 8B aligned)
        const float2 u0 = *reinterpret_cast<const float2*>(&unary[gg]);
        const float2 u1 = *reinterpret_cast<const float2*>(&unary[gg + HWn]);
        const float2 u2v = *reinterpret_cast<const float2*>(&unary[gg + 2 * HWn]);
        const float2 u3 = *reinterpret_cast<const float2*>(&unary[gg + 3 * HWn]);

        float4 resA, resB;
        {
            const __half2 wk01 = __hmul2(sA01, __hfma2(wa01, aA01, ws01));
            const __half2 wk23 = __hmul2(sA23, __hfma2(wa23, aA23, ws23));
            __half2 pw01 = __hmul2(__low2half2(wk01), ccA0);
            pw01 = __hfma2(__high2half2(wk01), ccA1, pw01);
            pw01 = __hfma2(__low2half2(wk23),  ccA2, pw01);
            pw01 = __hfma2(__high2half2(wk23), ccA3, pw01);
            __half2 pw23 = __hmul2(__low2half2(wk01), ccB0);
            pw23 = __hfma2(__high2half2(wk01), ccB1, pw23);
            pw23 = __hfma2(__low2half2(wk23),  ccB2, pw23);
            pw23 = __hfma2(__high2half2(wk23), ccB3, pw23);
            const float2 p01 = __half22float2(pw01);
            const float2 p23 = __half22float2(pw23);
            resA = make_float4(u0.x - p01.x, u1.x - p01.y,
                               u2v.x - p23.x, u3.x - p23.y);
        }
        {
            const __half2 wk01 = __hmul2(sB01, __hfma2(wa01, aB01, ws01));
            const __half2 wk23 = __hmul2(sB23, __hfma2(wa23, aB23, ws23));
            __half2 pw01 = __hmul2(__low2half2(wk01), ccA0);
            pw01 = __hfma2(__high2half2(wk01), ccA1, pw01);
            pw01 = __hfma2(__low2half2(wk23),  ccA2, pw01);
            pw01 = __hfma2(__high2half2(wk23), ccA3, pw01);
            __half2 pw23 = __hmul2(__low2half2(wk01), ccB0);
            pw23 = __hfma2(__high2half2(wk01), ccB1, pw23);
            pw23 = __hfma2(__low2half2(wk23),  ccB2, pw23);
            pw23 = __hfma2(__high2half2(wk23), ccB3, pw23);
            const float2 p01 = __half22float2(pw01);
            const float2 p23 = __half22float2(pw23);
            resB = make_float4(u0.y - p01.x, u1.y - p01.y,
                               u2v.y - p23.x, u3.y - p23.y);
        }

        if (LAST) {
            *reinterpret_cast<float2*>(&out[gg]) =
                make_float2(resA.x, resB.x);
            *reinterpret_cast<float2*>(&out[gg + HWn]) =
                make_float2(resA.y, resB.y);
            *reinterpret_cast<float2*>(&out[gg + 2 * HWn]) =
                make_float2(resA.z, resB.z);
            *reinterpret_cast<float2*>(&out[gg + 3 * HWn]) =
                make_float2(resA.w, resB.w);
        } else {
            const float4 smA = softmax4(resA);
            const float4 smB = softmax4(resB);
            *reinterpret_cast<uint4*>(&sQout[c]) =
                make_uint4(h2u(__floats2half2_rn(smA.x, smA.y)),
                           h2u(__floats2half2_rn(smA.z, smA.w)),
                           h2u(__floats2half2_rn(smB.x, smB.y)),
                           h2u(__floats2half2_rn(smB.z, smB.w)));
        }
    };

    {
        const int px = tid & 63;
        for (int r = UR0 + (tid >> 6); r < UR1; r += NTHREADS >> 6)
            u_pair(r, HC0 + 2 * px);
        if (EP > 0) {
            const int px2 = 64 + (tid & (EP - 1));
            const int r = UR0 + (tid >> LOG2EP);
            if (r < UR1) u_pair(r, HC0 + 2 * px2);
        }
    }
    if (!LAST) __syncthreads();
}

// ============================================================================
// Fused kernel: 3 CRF iterations, Q in fp16 smem, ping-pong buffers.
// ============================================================================
__global__ __launch_bounds__(NTHREADS, 3)
void crf_fused(const float* __restrict__ unary,
               const float* __restrict__ wapp,
               const float* __restrict__ wsmo,
               const float* __restrict__ compat,
               float*       __restrict__ out)
{
    extern __shared__ uint2 smem[];
    uint2* sA = smem;
    uint2* sB = smem + NEXT;
    uint2* sH = smem + 2 * NEXT;

    const int b   = blockIdx.z;
    const int ty0 = blockIdx.y * TY;
    const int tx0 = blockIdx.x * TX;
    const int tid = threadIdx.x;

    // Uniform parameters -> packed half2
    const __half2 w1h  = __float2half2_rn(W1f);
    const __half2 w4h  = __float2half2_rn(W4f);
    const __half2 wa01 = __floats2half2_rn(wapp[0], wapp[1]);
    const __half2 wa23 = __floats2half2_rn(wapp[2], wapp[3]);
    const __half2 ws01 = __floats2half2_rn(wsmo[0], wsmo[1]);
    const __half2 ws23 = __floats2half2_rn(wsmo[2], wsmo[3]);
    const __half2 ccA0 = __floats2half2_rn(compat[0],  compat[4]);
    const __half2 ccA1 = __floats2half2_rn(compat[1],  compat[5]);
    const __half2 ccA2 = __floats2half2_rn(compat[2],  compat[6]);
    const __half2 ccA3 = __floats2half2_rn(compat[3],  compat[7]);
    const __half2 ccB0 = __floats2half2_rn(compat[8],  compat[12]);
    const __half2 ccB1 = __floats2half2_rn(compat[9],  compat[13]);
    const __half2 ccB2 = __floats2half2_rn(compat[10], compat[14]);
    const __half2 ccB3 = __floats2half2_rn(compat[11], compat[15]);

    // ---- Phase 0: softmax(unary) over the full extended tile -> sA ----
    for (int i = tid; i < NEXT; i += NTHREADS) {
        const int row = i / EX;
        const int col = i - row * EX;
        const int gy = ty0 + row - 3;
        const int gx = tx0 + col - 6;
        uint2 q = make_uint2(0u, 0u);
        if (gy >= 0 && gy < Hn && gx >= 0 && gx < Wn) {
            const int gg = b * CHWn + gy * Wn + gx;
            const float4 sm = softmax4(make_float4(unary[gg],
                                                   unary[gg + HWn],
                                                   unary[gg + 2 * HWn],
                                                   unary[gg + 3 * HWn]));
            q = make_uint2(h2u(__floats2half2_rn(sm.x, sm.y)),
                           h2u(__floats2half2_rn(sm.z, sm.w)));
        }
        sA[i] = q;
    }
    __syncthreads();

    crf_do_iter<0, false>(sA, sB, sH, b, ty0, tx0, tid, unary, out,
                          w1h, w4h, wa01, wa23, ws01, ws23,
                          ccA0, ccA1, ccA2, ccA3, ccB0, ccB1, ccB2, ccB3);
    crf_do_iter<1, false>(sB, sA, sH, b, ty0, tx0, tid, unary, out,
                          w1h, w4h, wa01, wa23, ws01, ws23,
                          ccA0, ccA1, ccA2, ccA3, ccB0, ccB1, ccB2, ccB3);
    crf_do_iter<2, true >(sA, sB, sH, b, ty0, tx0, tid, unary, out,
                          w1h, w4h, wa01, wa23, ws01, ws23,
                          ccA0, ccA1, ccA2, ccA3, ccB0, ccB1, ccB2, ccB3);
}

extern "C" void kernel_launch(void* const* d_in, const int* in_sizes, int n_in,
                              void* d_out, int out_size)
{
    const float* unary  = (const float*)d_in[0];
    const float* xyz    = (const float*)d_in[1];
    const float* mask   = (const float*)d_in[2];
    const float* wapp   = (const float*)d_in[3];
    const float* wsmo   = (const float*)d_in[4];
    const float* compat = (const float*)d_in[5];
    float* out = (float*)d_out;

    cudaFuncSetAttribute(crf_fused, cudaFuncAttributeMaxDynamicSharedMemorySize,
                         SMEM_BYTES);

    dim3 sgrid(Wn / TX, Hn / STY, Bn);
    crf_setup<<<sgrid, SNT>>>(xyz, mask);

    dim3 grid(Wn / TX, Hn / TY, Bn);
    crf_fused<<<grid, NTHREADS, SMEM_BYTES>>>(unary, wapp, wsmo, compat, out);
}